// round 2
// baseline (speedup 1.0000x reference)
#include <cuda_runtime.h>
#include <cuda_bf16.h>

// ---------------------------------------------------------------------------
// GaussianVoxelizer: density[n] = sum_g op_g * exp(-0.5 * (c_n-m_g)^T Pinv_g (c_n-m_g))
// Inputs (metadata order): means3d [G,3] f32, opacities [G] f32,
//   covariances [G,3,3] f32, grid_coords [Nx,Ny,Nz,3] f32, vol_range [6] f32
// Output: [Nx,Ny,Nz,1] f32
// ---------------------------------------------------------------------------

#define GMAX 4096
#define TILE 1024

// Precomputed per-gaussian data (device-global scratch: no allocations allowed)
__device__ float4 g_m[GMAX];   // mean.x, mean.y, mean.z, opacity (0 if masked)
__device__ float4 g_p[GMAX];   // q00, 2*q01, 2*q02, q11   (q = -0.5*log2(e)*Pinv)
__device__ float2 g_q[GMAX];   // 2*q12, q22

__device__ __forceinline__ float ex2_approx(float x) {
    float y;
    asm("ex2.approx.ftz.f32 %0, %1;" : "=f"(y) : "f"(x));
    return y;
}

__global__ void gv_precompute(const float* __restrict__ means,
                              const float* __restrict__ ops,
                              const float* __restrict__ covs,
                              const float* __restrict__ vr,
                              int G) {
    int g = blockIdx.x * blockDim.x + threadIdx.x;
    if (g >= G) return;

    // Symmetric covariance entries
    float a = covs[9 * g + 0];
    float b = covs[9 * g + 1];
    float c = covs[9 * g + 2];
    float d = covs[9 * g + 4];
    float e = covs[9 * g + 5];
    float f = covs[9 * g + 8];

    // Adjugate / determinant inverse of symmetric 3x3
    float C00 = d * f - e * e;
    float C01 = c * e - b * f;
    float C02 = b * e - c * d;
    float C11 = a * f - c * c;
    float C12 = b * c - a * e;
    float C22 = a * d - b * b;
    float det = a * C00 + b * C01 + c * C02;
    float idet = 1.0f / det;

    // Fold -0.5 * log2(e) so the hot loop feeds ex2 directly
    const float S = -0.72134752044448170f;  // -0.5 * log2(e)
    float s = S * idet;

    float mx = means[3 * g + 0];
    float my = means[3 * g + 1];
    float mz = means[3 * g + 2];

    float sx = 3.0f * sqrtf(a);
    float sy = 3.0f * sqrtf(d);
    float sz = 3.0f * sqrtf(f);

    bool mask = (mx + sx > vr[0]) && (my + sy > vr[1]) && (mz + sz > vr[2]) &&
                (mx - sx < vr[3]) && (my - sy < vr[4]) && (mz - sz < vr[5]);
    float op = mask ? ops[g] : 0.0f;

    g_m[g] = make_float4(mx, my, mz, op);
    g_p[g] = make_float4(s * C00, 2.0f * s * C01, 2.0f * s * C02, s * C11);
    g_q[g] = make_float2(2.0f * s * C12, s * C22);
}

template <int VPT>
__global__ __launch_bounds__(256) void gv_voxelize(
    const float* __restrict__ coords,
    float* __restrict__ out,
    int N, int G) {
    __shared__ float4 s_m[TILE];
    __shared__ float4 s_p[TILE];
    __shared__ float2 s_q[TILE];

    const int tid = threadIdx.x;
    const int base = blockIdx.x * blockDim.x * VPT;

    float cx[VPT], cy[VPT], cz[VPT], acc[VPT];
    bool valid[VPT];
#pragma unroll
    for (int v = 0; v < VPT; ++v) {
        int idx = base + v * blockDim.x + tid;
        valid[v] = idx < N;
        int li = valid[v] ? idx : 0;
        cx[v] = coords[3 * li + 0];
        cy[v] = coords[3 * li + 1];
        cz[v] = coords[3 * li + 2];
        acc[v] = 0.0f;
    }

    for (int gbase = 0; gbase < G; gbase += TILE) {
        int tcount = min(TILE, G - gbase);
        // Cooperative stage of gaussian params into shared memory
        for (int i = tid; i < tcount; i += blockDim.x) {
            s_m[i] = g_m[gbase + i];
            s_p[i] = g_p[gbase + i];
            s_q[i] = g_q[gbase + i];
        }
        __syncthreads();

#pragma unroll 4
        for (int g = 0; g < tcount; ++g) {
            float4 m = s_m[g];
            float4 p = s_p[g];
            float2 q = s_q[g];
#pragma unroll
            for (int v = 0; v < VPT; ++v) {
                float dx = cx[v] - m.x;
                float dy = cy[v] - m.y;
                float dz = cz[v] - m.z;
                // quadratic form with folded -0.5*log2(e)
                float t0 = fmaf(p.x, dx, fmaf(p.y, dy, p.z * dz));
                float t1 = fmaf(p.w, dy, q.x * dz);
                float ee = fmaf(dx, t0, fmaf(dy, t1, (q.y * dz) * dz));
                float w = ex2_approx(ee);
                acc[v] = fmaf(m.w, w, acc[v]);
            }
        }
        __syncthreads();
    }

#pragma unroll
    for (int v = 0; v < VPT; ++v) {
        int idx = base + v * blockDim.x + tid;
        if (valid[v]) out[idx] = acc[v];
    }
}

extern "C" void kernel_launch(void* const* d_in, const int* in_sizes, int n_in,
                              void* d_out, int out_size) {
    const float* means  = (const float*)d_in[0];
    const float* ops    = (const float*)d_in[1];
    const float* covs   = (const float*)d_in[2];
    const float* coords = (const float*)d_in[3];
    const float* vr     = (const float*)d_in[4];
    float* out = (float*)d_out;

    int G = in_sizes[1];          // opacity count
    if (G > GMAX) G = GMAX;
    int N = in_sizes[3] / 3;      // voxel count

    // 1) Precompute per-gaussian inverse covariance + mask fold
    int pb = (G + 255) / 256;
    gv_precompute<<<pb, 256>>>(means, ops, covs, vr, G);

    // 2) Voxelize: 256 threads, 2 voxels/thread -> 512 voxels/block
    constexpr int VPT = 2;
    int blocks = (N + 256 * VPT - 1) / (256 * VPT);
    gv_voxelize<VPT><<<blocks, 256>>>(coords, out, N, G);
}

// round 3
// speedup vs baseline: 1.6554x; 1.6554x over previous
#include <cuda_runtime.h>
#include <cuda_bf16.h>

// ---------------------------------------------------------------------------
// GaussianVoxelizer: density[n] = sum_g op_g * exp(-0.5 * (c_n-m_g)^T Pinv_g (c_n-m_g))
// Strategy:
//   precompute: per-gaussian inverse covariance, fold -0.5*log2(e) and the 2x
//     off-diag factors, fold the bounds mask into opacity, store NEGATED means,
//     and pack gaussians in PAIRS (pair-interleaved floats) so the hot loop can
//     use fma.rn.f32x2 packed math with operands loaded directly via LDS.128.
//   voxelize: grid.y = GSPLIT splits of the gaussian range per voxel (raises
//     occupancy 4x on this work-starved problem); each split writes a private
//     partial buffer (no atomics -> deterministic).
//   reduce: out[i] = sum over splits of partial[s][i].
// ---------------------------------------------------------------------------

#define GMAX   4096
#define GPAIR_MAX (GMAX / 2)
#define GSPLIT 4
#define NPAD   131072
#define PAIRS_TILE 128   // pairs staged in smem per block tile (80B each)

// Packed per-pair records: 5 x ulonglong2 (= 20 floats) per gaussian pair.
// float layout within record:
//  [0,1]=-mx  [2,3]=-my  [4,5]=-mz  [6,7]=op
//  [8,9]=q00 [10,11]=2q01 [12,13]=2q02 [14,15]=q11 [16,17]=2q12 [18,19]=q22
//  (q = -0.5*log2(e) * inv(cov); lane 0/1 = gaussians 2p / 2p+1)
__device__ ulonglong2 g_rec[GPAIR_MAX * 5];
__device__ float g_part[GSPLIT * NPAD];

__device__ __forceinline__ float ex2_approx(float x) {
    float y;
    asm("ex2.approx.ftz.f32 %0, %1;" : "=f"(y) : "f"(x));
    return y;
}
__device__ __forceinline__ unsigned long long pack_x2(float lo, float hi) {
    unsigned long long r;
    asm("mov.b64 %0, {%1, %2};" : "=l"(r) : "f"(lo), "f"(hi));
    return r;
}
__device__ __forceinline__ void unpack_x2(unsigned long long v, float& lo, float& hi) {
    asm("mov.b64 {%0, %1}, %2;" : "=f"(lo), "=f"(hi) : "l"(v));
}
__device__ __forceinline__ unsigned long long add_x2(unsigned long long a, unsigned long long b) {
    unsigned long long d;
    asm("add.rn.f32x2 %0, %1, %2;" : "=l"(d) : "l"(a), "l"(b));
    return d;
}
__device__ __forceinline__ unsigned long long mul_x2(unsigned long long a, unsigned long long b) {
    unsigned long long d;
    asm("mul.rn.f32x2 %0, %1, %2;" : "=l"(d) : "l"(a), "l"(b));
    return d;
}
__device__ __forceinline__ unsigned long long fma_x2(unsigned long long a, unsigned long long b,
                                                     unsigned long long c) {
    unsigned long long d;
    asm("fma.rn.f32x2 %0, %1, %2, %3;" : "=l"(d) : "l"(a), "l"(b), "l"(c));
    return d;
}

__global__ void gv_precompute(const float* __restrict__ means,
                              const float* __restrict__ ops,
                              const float* __restrict__ covs,
                              const float* __restrict__ vr,
                              int G, int Gpad) {
    int g = blockIdx.x * blockDim.x + threadIdx.x;
    if (g >= Gpad) return;

    float* rec = (float*)g_rec;
    int pair = g >> 1;
    int lane = g & 1;
    float* r = rec + pair * 20 + lane;

    if (g >= G) {  // padding: contributes op=0, ee=0 -> 0
        #pragma unroll
        for (int f = 0; f < 10; ++f) r[2 * f] = 0.0f;
        return;
    }

    float a = covs[9 * g + 0];
    float b = covs[9 * g + 1];
    float c = covs[9 * g + 2];
    float d = covs[9 * g + 4];
    float e = covs[9 * g + 5];
    float f = covs[9 * g + 8];

    float C00 = d * f - e * e;
    float C01 = c * e - b * f;
    float C02 = b * e - c * d;
    float C11 = a * f - c * c;
    float C12 = b * c - a * e;
    float C22 = a * d - b * b;
    float det = a * C00 + b * C01 + c * C02;
    float idet = 1.0f / det;

    const float S = -0.72134752044448170f;  // -0.5 * log2(e)
    float s = S * idet;

    float mx = means[3 * g + 0];
    float my = means[3 * g + 1];
    float mz = means[3 * g + 2];

    float sx = 3.0f * sqrtf(a);
    float sy = 3.0f * sqrtf(d);
    float sz = 3.0f * sqrtf(f);
    bool mask = (mx + sx > vr[0]) && (my + sy > vr[1]) && (mz + sz > vr[2]) &&
                (mx - sx < vr[3]) && (my - sy < vr[4]) && (mz - sz < vr[5]);
    float op = mask ? ops[g] : 0.0f;

    r[0]  = -mx;
    r[2]  = -my;
    r[4]  = -mz;
    r[6]  = op;
    r[8]  = s * C00;
    r[10] = 2.0f * s * C01;
    r[12] = 2.0f * s * C02;
    r[14] = s * C11;
    r[16] = 2.0f * s * C12;
    r[18] = s * C22;
}

template <int VPT>
__global__ __launch_bounds__(256) void gv_voxelize(
    const float* __restrict__ coords,
    int N, int npairs) {
    __shared__ ulonglong2 s_rec[PAIRS_TILE * 5];

    const int tid = threadIdx.x;
    const int base = blockIdx.x * blockDim.x * VPT;
    const int split = blockIdx.y;

    // This split's pair range
    const int pairs_per_split = (npairs + GSPLIT - 1) / GSPLIT;
    const int p_lo = split * pairs_per_split;
    const int p_hi = min(npairs, p_lo + pairs_per_split);

    unsigned long long cxx[VPT], cyy[VPT], czz[VPT];
    float acc[VPT];
    bool valid[VPT];
#pragma unroll
    for (int v = 0; v < VPT; ++v) {
        int idx = base + v * blockDim.x + tid;
        valid[v] = idx < N;
        int li = valid[v] ? idx : 0;
        float cx = coords[3 * li + 0];
        float cy = coords[3 * li + 1];
        float cz = coords[3 * li + 2];
        cxx[v] = pack_x2(cx, cx);
        cyy[v] = pack_x2(cy, cy);
        czz[v] = pack_x2(cz, cz);
        acc[v] = 0.0f;
    }

    for (int pbase = p_lo; pbase < p_hi; pbase += PAIRS_TILE) {
        int tcount = min(PAIRS_TILE, p_hi - pbase);
        // Stage pair records to smem (tcount * 5 ulonglong2)
        for (int i = tid; i < tcount * 5; i += blockDim.x)
            s_rec[i] = g_rec[pbase * 5 + i];
        __syncthreads();

#pragma unroll 2
        for (int p = 0; p < tcount; ++p) {
            ulonglong2 r0 = s_rec[5 * p + 0];  // {-mx, -my}
            ulonglong2 r1 = s_rec[5 * p + 1];  // {-mz, op}
            ulonglong2 r2 = s_rec[5 * p + 2];  // {q00, 2q01}
            ulonglong2 r3 = s_rec[5 * p + 3];  // {2q02, q11}
            ulonglong2 r4 = s_rec[5 * p + 4];  // {2q12, q22}
            float op0, op1;
            unpack_x2(r1.y, op0, op1);
#pragma unroll
            for (int v = 0; v < VPT; ++v) {
                unsigned long long dx = add_x2(cxx[v], r0.x);
                unsigned long long dy = add_x2(cyy[v], r0.y);
                unsigned long long dz = add_x2(czz[v], r1.x);
                unsigned long long t0 =
                    fma_x2(r2.x, dx, fma_x2(r2.y, dy, mul_x2(r3.x, dz)));
                unsigned long long t1 = fma_x2(r3.y, dy, mul_x2(r4.x, dz));
                unsigned long long t2 = mul_x2(mul_x2(r4.y, dz), dz);
                unsigned long long ee = fma_x2(dx, t0, fma_x2(dy, t1, t2));
                float e0, e1;
                unpack_x2(ee, e0, e1);
                float w0 = ex2_approx(e0);
                float w1 = ex2_approx(e1);
                acc[v] = fmaf(op0, w0, acc[v]);
                acc[v] = fmaf(op1, w1, acc[v]);
            }
        }
        __syncthreads();
    }

#pragma unroll
    for (int v = 0; v < VPT; ++v) {
        int idx = base + v * blockDim.x + tid;
        if (valid[v]) g_part[split * NPAD + idx] = acc[v];
    }
}

__global__ void gv_reduce4(float* __restrict__ out, int N4) {
    int i = blockIdx.x * blockDim.x + threadIdx.x;
    if (i >= N4) return;
    const float4* p0 = (const float4*)(g_part + 0 * NPAD);
    const float4* p1 = (const float4*)(g_part + 1 * NPAD);
    const float4* p2 = (const float4*)(g_part + 2 * NPAD);
    const float4* p3 = (const float4*)(g_part + 3 * NPAD);
    float4 a = p0[i], b = p1[i], c = p2[i], d = p3[i];
    float4 r;
    r.x = (a.x + b.x) + (c.x + d.x);
    r.y = (a.y + b.y) + (c.y + d.y);
    r.z = (a.z + b.z) + (c.z + d.z);
    r.w = (a.w + b.w) + (c.w + d.w);
    ((float4*)out)[i] = r;
}

__global__ void gv_reduce1(float* __restrict__ out, int N) {
    int i = blockIdx.x * blockDim.x + threadIdx.x;
    if (i >= N) return;
    float s = 0.0f;
#pragma unroll
    for (int k = 0; k < GSPLIT; ++k) s += g_part[k * NPAD + i];
    out[i] = s;
}

extern "C" void kernel_launch(void* const* d_in, const int* in_sizes, int n_in,
                              void* d_out, int out_size) {
    const float* means  = (const float*)d_in[0];
    const float* ops    = (const float*)d_in[1];
    const float* covs   = (const float*)d_in[2];
    const float* coords = (const float*)d_in[3];
    const float* vr     = (const float*)d_in[4];
    float* out = (float*)d_out;

    int G = in_sizes[1];
    if (G > GMAX) G = GMAX;
    int N = in_sizes[3] / 3;
    if (N > NPAD) N = NPAD;

    int npairs = (G + 1) / 2;
    int Gpad = npairs * 2;

    // 1) Precompute packed-pair gaussian records
    int pb = (Gpad + 255) / 256;
    gv_precompute<<<pb, 256>>>(means, ops, covs, vr, G, Gpad);

    // 2) Voxelize with G split across grid.y, partials per split
    constexpr int VPT = 2;
    dim3 grid((N + 256 * VPT - 1) / (256 * VPT), GSPLIT);
    gv_voxelize<VPT><<<grid, 256>>>(coords, N, npairs);

    // 3) Reduce partials
    if ((N & 3) == 0) {
        int n4 = N / 4;
        gv_reduce4<<<(n4 + 255) / 256, 256>>>(out, n4);
    } else {
        gv_reduce1<<<(N + 255) / 256, 256>>>(out, N);
    }
}

// round 4
// speedup vs baseline: 5.9115x; 3.5712x over previous
#include <cuda_runtime.h>
#include <cuda_bf16.h>

// ---------------------------------------------------------------------------
// GaussianVoxelizer, fused single kernel:
//   density[n] = sum_g op_g * exp(-0.5 * (c_n - m_g)^T inv(Sigma_g) (c_n - m_g))
//
// Each block owns a spatial tile of voxels. It:
//   1. computes the tile's coordinate AABB (warp/smem min-max reduction),
//   2. culls gaussians whose 9-sigma per-axis reach misses the AABB
//      (safe: maha >= d_i^2 / Sigma_ii, so culled weight < exp(-40.5)),
//   3. for survivors, computes inv covariance (folding -0.5*log2(e), the
//      2x off-diagonal factors, and the vol-range mask into the record),
//      compacted into smem with deterministic ballot+prefix (no atomics),
//   4. evaluates the ~90 surviving gaussians per voxel with scalar FMA + ex2.
// No precompute kernel, no reduce kernel, no partial buffers.
// ---------------------------------------------------------------------------

#define GCHUNK 1024
#define CULL_K2 81.0f   // (9 sigma)^2

__device__ __forceinline__ float ex2_approx(float x) {
    float y;
    asm("ex2.approx.ftz.f32 %0, %1;" : "=f"(y) : "f"(x));
    return y;
}

template <bool TILED>
__global__ __launch_bounds__(256) void gv_fused(
    const float* __restrict__ means,
    const float* __restrict__ ops,
    const float* __restrict__ covs,
    const float* __restrict__ coords,
    const float* __restrict__ vr,
    float* __restrict__ out,
    int G, int N, int NX, int NY, int NZ) {
    __shared__ float4 s_a[GCHUNK];      // -mx, -my, -mz, op
    __shared__ float4 s_b[GCHUNK];      // q00, 2q01, 2q02, q11
    __shared__ float2 s_c[GCHUNK];      // 2q12, q22
    __shared__ float s_lo[3][8], s_hi[3][8];
    __shared__ int s_wcnt[8];
    __shared__ int s_total;

    const int tid = threadIdx.x;
    const int lane = tid & 31;
    const int wid = tid >> 5;

    // ---- thread -> voxel mapping ----
    int vidx;
    bool valid;
    if (TILED) {
        // tile = 8 x 8 x 4 voxels; tz = bits[0:2), ty = bits[2:5), tx = bits[5:8)
        int tz = tid & 3;
        int ty = (tid >> 2) & 7;
        int tx = tid >> 5;
        int X = blockIdx.x * 8 + tx;
        int Y = blockIdx.y * 8 + ty;
        int Z = blockIdx.z * 4 + tz;
        valid = (X < NX) && (Y < NY) && (Z < NZ);
        if (X >= NX) X = NX - 1;
        if (Y >= NY) Y = NY - 1;
        if (Z >= NZ) Z = NZ - 1;
        vidx = (X * NY + Y) * NZ + Z;
    } else {
        vidx = blockIdx.x * 256 + tid;
        valid = vidx < N;
        if (!valid) vidx = N - 1;
    }

    const float cx = coords[3 * vidx + 0];
    const float cy = coords[3 * vidx + 1];
    const float cz = coords[3 * vidx + 2];

    // ---- block AABB (min/max reduction over this block's coords) ----
    float lox = cx, hix = cx, loy = cy, hiy = cy, loz = cz, hiz = cz;
#pragma unroll
    for (int off = 16; off; off >>= 1) {
        lox = fminf(lox, __shfl_xor_sync(0xffffffffu, lox, off));
        hix = fmaxf(hix, __shfl_xor_sync(0xffffffffu, hix, off));
        loy = fminf(loy, __shfl_xor_sync(0xffffffffu, loy, off));
        hiy = fmaxf(hiy, __shfl_xor_sync(0xffffffffu, hiy, off));
        loz = fminf(loz, __shfl_xor_sync(0xffffffffu, loz, off));
        hiz = fmaxf(hiz, __shfl_xor_sync(0xffffffffu, hiz, off));
    }
    if (lane == 0) {
        s_lo[0][wid] = lox; s_hi[0][wid] = hix;
        s_lo[1][wid] = loy; s_hi[1][wid] = hiy;
        s_lo[2][wid] = loz; s_hi[2][wid] = hiz;
    }
    __syncthreads();
#pragma unroll
    for (int w = 0; w < 8; ++w) {
        lox = fminf(lox, s_lo[0][w]); hix = fmaxf(hix, s_hi[0][w]);
        loy = fminf(loy, s_lo[1][w]); hiy = fmaxf(hiy, s_hi[1][w]);
        loz = fminf(loz, s_lo[2][w]); hiz = fmaxf(hiz, s_hi[2][w]);
    }

    const float v0 = vr[0], v1 = vr[1], v2 = vr[2];
    const float v3 = vr[3], v4 = vr[4], v5 = vr[5];

    float acc = 0.0f;

    for (int gbase = 0; gbase < G; gbase += GCHUNK) {
        if (tid == 0) s_total = 0;
        __syncthreads();
        const int chunk = min(GCHUNK, G - gbase);

        // ---- cull + compact (deterministic order: pass-major, warp, lane) ----
        for (int p = 0; p < GCHUNK; p += 256) {
            const int g = gbase + p + tid;
            bool survive = false;
            float caa = 1, cab = 0, cac = 0, cbb = 1, cbc = 0, ccc = 1;
            float mx = 0, my = 0, mz = 0, op = 0;
            if (p + tid < chunk) {
                mx = means[3 * g + 0];
                my = means[3 * g + 1];
                mz = means[3 * g + 2];
                caa = covs[9 * g + 0];
                cab = covs[9 * g + 1];
                cac = covs[9 * g + 2];
                cbb = covs[9 * g + 4];
                cbc = covs[9 * g + 5];
                ccc = covs[9 * g + 8];
                op = ops[g];

                // reference's volume-range mask (3 sigma)
                float sx = 3.0f * sqrtf(caa);
                float sy = 3.0f * sqrtf(cbb);
                float sz = 3.0f * sqrtf(ccc);
                bool mask = (mx + sx > v0) && (my + sy > v1) && (mz + sz > v2) &&
                            (mx - sx < v3) && (my - sy < v4) && (mz - sz < v5);

                // conservative 9-sigma AABB cull (per-axis marginal bound)
                float gx = fmaxf(fmaxf(lox - mx, mx - hix), 0.0f);
                float gy = fmaxf(fmaxf(loy - my, my - hiy), 0.0f);
                float gz = fmaxf(fmaxf(loz - mz, mz - hiz), 0.0f);
                survive = mask && (op != 0.0f) &&
                          (gx * gx <= CULL_K2 * caa) &&
                          (gy * gy <= CULL_K2 * cbb) &&
                          (gz * gz <= CULL_K2 * ccc);
            }
            unsigned m = __ballot_sync(0xffffffffu, survive);
            if (lane == 0) s_wcnt[wid] = __popc(m);
            __syncthreads();
            int base = s_total;
#pragma unroll
            for (int w = 0; w < 8; ++w)
                if (w < wid) base += s_wcnt[w];
            if (survive) {
                int pos = base + __popc(m & ((1u << lane) - 1u));
                // inverse of symmetric 3x3 via adjugate
                float C00 = cbb * ccc - cbc * cbc;
                float C01 = cac * cbc - cab * ccc;
                float C02 = cab * cbc - cac * cbb;
                float C11 = caa * ccc - cac * cac;
                float C12 = cab * cac - caa * cbc;
                float C22 = caa * cbb - cab * cab;
                float det = caa * C00 + cab * C01 + cac * C02;
                float s = -0.72134752044448170f / det;  // -0.5*log2(e)/det
                s_a[pos] = make_float4(-mx, -my, -mz, op);
                s_b[pos] = make_float4(s * C00, 2.0f * s * C01, 2.0f * s * C02, s * C11);
                s_c[pos] = make_float2(2.0f * s * C12, s * C22);
            }
            __syncthreads();
            if (tid == 0) {
                int t = 0;
#pragma unroll
                for (int w = 0; w < 8; ++w) t += s_wcnt[w];
                s_total += t;
            }
            __syncthreads();
        }

        // ---- evaluate survivors ----
        const int cnt = s_total;
#pragma unroll 4
        for (int i = 0; i < cnt; ++i) {
            float4 A = s_a[i];
            float4 B = s_b[i];
            float2 C = s_c[i];
            float dx = cx + A.x;
            float dy = cy + A.y;
            float dz = cz + A.z;
            float t0 = fmaf(B.x, dx, fmaf(B.y, dy, B.z * dz));
            float t1 = fmaf(B.w, dy, C.x * dz);
            float ee = fmaf(dx, t0, fmaf(dy, t1, (C.y * dz) * dz));
            acc = fmaf(A.w, ex2_approx(ee), acc);
        }
        __syncthreads();
    }

    if (valid) out[vidx] = acc;
}

extern "C" void kernel_launch(void* const* d_in, const int* in_sizes, int n_in,
                              void* d_out, int out_size) {
    const float* means  = (const float*)d_in[0];
    const float* ops    = (const float*)d_in[1];
    const float* covs   = (const float*)d_in[2];
    const float* coords = (const float*)d_in[3];
    const float* vr     = (const float*)d_in[4];
    float* out = (float*)d_out;

    int G = in_sizes[1];
    int N = in_sizes[3] / 3;

    const int NX = 100, NY = 100, NZ = 8;
    if (N == NX * NY * NZ) {
        dim3 grid((NX + 7) / 8, (NY + 7) / 8, (NZ + 3) / 4);
        gv_fused<true><<<grid, 256>>>(means, ops, covs, coords, vr, out,
                                      G, N, NX, NY, NZ);
    } else {
        int blocks = (N + 255) / 256;
        gv_fused<false><<<blocks, 256>>>(means, ops, covs, coords, vr, out,
                                         G, N, 0, 0, 0);
    }
}